// round 6
// baseline (speedup 1.0000x reference)
#include <cuda_runtime.h>

// ---------------------------------------------------------------------------
// Attention_87557203296748 — full MHA block, fp32 baseline.
//   1) qkv = x @ w_qkv^T        (8192 x 3072 x 1024), scatter to Q/K/V [B,H,N,HD]
//   2) flash attention per (b,h), q-tile 64, kv-tile 64, online softmax
//   3) out = attn_out @ w_proj^T + b_proj  (8192 x 1024 x 1024)
// All fp32 -> rel_err ~1e-6. Three kernel launches, graph-capturable,
// scratch in __device__ globals (no allocations).
// ---------------------------------------------------------------------------

#define BATCH  4
#define SEQ    2048
#define DIM    1024
#define NH     16
#define HDIM   64
#define QSCALE 0.125f          // HD^-0.5 = 1/8
#define MTOT   (BATCH * SEQ)   // 8192

__device__ float g_q [(size_t)BATCH * NH * SEQ * HDIM];  // 32 MB
__device__ float g_k [(size_t)BATCH * NH * SEQ * HDIM];  // 32 MB
__device__ float g_v [(size_t)BATCH * NH * SEQ * HDIM];  // 32 MB
__device__ float g_ao[(size_t)MTOT * DIM];               // 32 MB, [B,N,H,HD] = [8192,1024]

// ---------------------------------------------------------------------------
// Tiled SGEMM, C[m,e] = sum_k A[m,k] * B[e,k]  (both row-major, K-contiguous).
// 128x128x16 tile, 256 threads, 8x8 per thread.
// MODE 0: A = x, B = w_qkv -> scatter into g_q/g_k/g_v (Q scaled).
// MODE 1: A = g_ao, B = w_proj -> Cout = C + bias.
// ---------------------------------------------------------------------------
template <int MODE>
__launch_bounds__(256, 2)
__global__ void gemm_nt_kernel(const float* __restrict__ Ain,
                               const float* __restrict__ Bw,
                               const float* __restrict__ bias,
                               float* __restrict__ Cout)
{
    const int K = 1024;
    __shared__ float As[16 * 132];   // [k][m], padded stride 132
    __shared__ float Bs[16 * 132];   // [k][e]

    const float* A = (MODE == 0) ? Ain : g_ao;

    const int tid = threadIdx.x;
    const int ty  = tid >> 4;        // 0..15, M direction
    const int tx  = tid & 15;        // 0..15, E direction
    const int m0  = blockIdx.y * 128;
    const int e0  = blockIdx.x * 128;

    float acc[8][8];
#pragma unroll
    for (int i = 0; i < 8; i++)
#pragma unroll
        for (int j = 0; j < 8; j++) acc[i][j] = 0.0f;

    for (int k0 = 0; k0 < K; k0 += 16) {
#pragma unroll
        for (int i = 0; i < 2; i++) {
            int id = tid + i * 256;          // 0..511
            int r  = id >> 2;                // 0..127 (tile row)
            int c4 = (id & 3) << 2;          // 0,4,8,12 (k offset)
            float4 va = *(const float4*)(A  + (size_t)(m0 + r) * K + k0 + c4);
            As[(c4 + 0) * 132 + r] = va.x;
            As[(c4 + 1) * 132 + r] = va.y;
            As[(c4 + 2) * 132 + r] = va.z;
            As[(c4 + 3) * 132 + r] = va.w;
            float4 vb = *(const float4*)(Bw + (size_t)(e0 + r) * K + k0 + c4);
            Bs[(c4 + 0) * 132 + r] = vb.x;
            Bs[(c4 + 1) * 132 + r] = vb.y;
            Bs[(c4 + 2) * 132 + r] = vb.z;
            Bs[(c4 + 3) * 132 + r] = vb.w;
        }
        __syncthreads();

#pragma unroll
        for (int kk = 0; kk < 16; kk++) {
            float a[8], b[8];
            *(float4*)&a[0] = *(float4*)&As[kk * 132 + ty * 8];
            *(float4*)&a[4] = *(float4*)&As[kk * 132 + ty * 8 + 4];
            *(float4*)&b[0] = *(float4*)&Bs[kk * 132 + tx * 8];
            *(float4*)&b[4] = *(float4*)&Bs[kk * 132 + tx * 8 + 4];
#pragma unroll
            for (int i = 0; i < 8; i++)
#pragma unroll
                for (int j = 0; j < 8; j++)
                    acc[i][j] = fmaf(a[i], b[j], acc[i][j]);
        }
        __syncthreads();
    }

    if (MODE == 0) {
        // e in [0,3072): c = e/1024 selects Q/K/V, h = (e%1024)/64, hd = e%64.
        // Each thread's 8 e's stay inside one (c,h) block (start % 8 == 0).
        const int e_base = e0 + tx * 8;
        const int c   = e_base >> 10;
        const int rem = e_base & 1023;
        const int h   = rem >> 6;
        const int hd0 = rem & 63;
        const float mul = (c == 0) ? QSCALE : 1.0f;
        float* buf = (c == 0) ? g_q : ((c == 1) ? g_k : g_v);
#pragma unroll
        for (int i = 0; i < 8; i++) {
            int m  = m0 + ty * 8 + i;
            int b_ = m >> 11;        // / 2048
            int n  = m & 2047;
            float* p = buf + ((size_t)((b_ * NH + h) * SEQ + n)) * HDIM + hd0;
            float4 v0 = make_float4(acc[i][0] * mul, acc[i][1] * mul,
                                    acc[i][2] * mul, acc[i][3] * mul);
            float4 v1 = make_float4(acc[i][4] * mul, acc[i][5] * mul,
                                    acc[i][6] * mul, acc[i][7] * mul);
            *(float4*)p       = v0;
            *(float4*)(p + 4) = v1;
        }
    } else {
        const int e_base = e0 + tx * 8;
        float4 bb0 = *(const float4*)(bias + e_base);
        float4 bb1 = *(const float4*)(bias + e_base + 4);
#pragma unroll
        for (int i = 0; i < 8; i++) {
            int m = m0 + ty * 8 + i;
            float* p = Cout + (size_t)m * 1024 + e_base;
            float4 v0 = make_float4(acc[i][0] + bb0.x, acc[i][1] + bb0.y,
                                    acc[i][2] + bb0.z, acc[i][3] + bb0.w);
            float4 v1 = make_float4(acc[i][4] + bb1.x, acc[i][5] + bb1.y,
                                    acc[i][6] + bb1.z, acc[i][7] + bb1.w);
            *(float4*)p       = v0;
            *(float4*)(p + 4) = v1;
        }
    }
}

// ---------------------------------------------------------------------------
// Flash attention, fp32. Grid: (32 q-tiles, 64 bh). 256 threads.
// Thread (ty,tx): ty=tid/16 owns q-rows 4ty..4ty+3, tx=tid%16 owns cols 4tx..4tx+3.
// The 16 lanes of one q-row group are contiguous within a warp -> shfl_xor(<=8)
// reduces rows. Q and K stored TRANSPOSED in smem; P stored transposed into the
// K buffer -> every inner-loop read is a conflict-free LDS.128 (2 loads / 16 FMA).
// ---------------------------------------------------------------------------
#define KP_STRIDE 68
#define FLASH_SMEM_BYTES ((64 * 64 + 64 * KP_STRIDE + 64 * 64) * 4)   // 50176

__launch_bounds__(256, 2)
__global__ void flash_kernel()
{
    extern __shared__ float sm[];
    float* QsT = sm;                       // [d=64][q=64], stride 64
    float* KP  = sm + 64 * 64;             // K^T [d][k] then P^T [k][q], stride 68
    float* Vs  = KP + 64 * KP_STRIDE;      // [k=64][d=64], stride 64

    const int tid = threadIdx.x;
    const int ty  = tid >> 4;
    const int tx  = tid & 15;
    const int qt  = blockIdx.x;            // 0..31
    const int bh  = blockIdx.y;            // 0..63

    const float* Qg = g_q + (size_t)bh * SEQ * HDIM + (size_t)qt * 64 * HDIM;
    const float* Kg = g_k + (size_t)bh * SEQ * HDIM;
    const float* Vg = g_v + (size_t)bh * SEQ * HDIM;

    // Load Q tile transposed (once per CTA; store conflicts amortized away).
#pragma unroll
    for (int i = 0; i < 4; i++) {
        int id = tid + i * 256;
        int r  = id >> 4;                  // 0..63 q-row
        int c  = (id & 15) << 2;           // 0..60 d
        float4 q4 = *(const float4*)(Qg + (size_t)r * HDIM + c);
        QsT[(c + 0) * 64 + r] = q4.x;
        QsT[(c + 1) * 64 + r] = q4.y;
        QsT[(c + 2) * 64 + r] = q4.z;
        QsT[(c + 3) * 64 + r] = q4.w;
    }

    float m_i[4], l_i[4], o[4][4];
#pragma unroll
    for (int i = 0; i < 4; i++) {
        m_i[i] = -1e30f;
        l_i[i] = 0.0f;
#pragma unroll
        for (int j = 0; j < 4; j++) o[i][j] = 0.0f;
    }

    for (int kt = 0; kt < SEQ / 64; kt++) {
        __syncthreads();   // previous PV reads of KP/Vs complete

        const float* kg = Kg + (size_t)kt * 64 * HDIM;
        const float* vg = Vg + (size_t)kt * 64 * HDIM;
#pragma unroll
        for (int i = 0; i < 4; i++) {
            int id = tid + i * 256;
            int r  = id >> 4;
            int c  = (id & 15) << 2;
            float4 k4 = *(const float4*)(kg + (size_t)r * HDIM + c);
            KP[(c + 0) * KP_STRIDE + r] = k4.x;
            KP[(c + 1) * KP_STRIDE + r] = k4.y;
            KP[(c + 2) * KP_STRIDE + r] = k4.z;
            KP[(c + 3) * KP_STRIDE + r] = k4.w;
            *(float4*)&Vs[r * 64 + c] = *(const float4*)(vg + (size_t)r * HDIM + c);
        }
        __syncthreads();

        // S[i][j] = sum_d Q[4ty+i][d] * K[4tx+j][d]
        float s[4][4];
#pragma unroll
        for (int i = 0; i < 4; i++)
#pragma unroll
            for (int j = 0; j < 4; j++) s[i][j] = 0.0f;

#pragma unroll 8
        for (int d = 0; d < 64; d++) {
            float4 qf = *(float4*)&QsT[d * 64 + (ty << 2)];
            float4 kf = *(float4*)&KP [d * KP_STRIDE + (tx << 2)];
            s[0][0] = fmaf(qf.x, kf.x, s[0][0]); s[0][1] = fmaf(qf.x, kf.y, s[0][1]);
            s[0][2] = fmaf(qf.x, kf.z, s[0][2]); s[0][3] = fmaf(qf.x, kf.w, s[0][3]);
            s[1][0] = fmaf(qf.y, kf.x, s[1][0]); s[1][1] = fmaf(qf.y, kf.y, s[1][1]);
            s[1][2] = fmaf(qf.y, kf.z, s[1][2]); s[1][3] = fmaf(qf.y, kf.w, s[1][3]);
            s[2][0] = fmaf(qf.z, kf.x, s[2][0]); s[2][1] = fmaf(qf.z, kf.y, s[2][1]);
            s[2][2] = fmaf(qf.z, kf.z, s[2][2]); s[2][3] = fmaf(qf.z, kf.w, s[2][3]);
            s[3][0] = fmaf(qf.w, kf.x, s[3][0]); s[3][1] = fmaf(qf.w, kf.y, s[3][1]);
            s[3][2] = fmaf(qf.w, kf.z, s[3][2]); s[3][3] = fmaf(qf.w, kf.w, s[3][3]);
        }

        // Online softmax per q-row (16-lane reductions).
        float p[4][4];
#pragma unroll
        for (int i = 0; i < 4; i++) {
            float mx = fmaxf(fmaxf(s[i][0], s[i][1]), fmaxf(s[i][2], s[i][3]));
#pragma unroll
            for (int w = 8; w >= 1; w >>= 1)
                mx = fmaxf(mx, __shfl_xor_sync(0xffffffffu, mx, w));
            float mnew = fmaxf(m_i[i], mx);
            float corr = __expf(m_i[i] - mnew);
            m_i[i] = mnew;
            float rs = 0.0f;
#pragma unroll
            for (int j = 0; j < 4; j++) {
                p[i][j] = __expf(s[i][j] - mnew);
                rs += p[i][j];
            }
#pragma unroll
            for (int w = 8; w >= 1; w >>= 1)
                rs += __shfl_xor_sync(0xffffffffu, rs, w);
            l_i[i] = l_i[i] * corr + rs;
#pragma unroll
            for (int j = 0; j < 4; j++) o[i][j] *= corr;
        }

        __syncthreads();   // all lanes done reading KP as K^T
        // Store P^T into KP: P[4ty+i][4tx+j] -> KP[(4tx+j)*68 + 4ty+i]
#pragma unroll
        for (int j = 0; j < 4; j++) {
            float4 pv = make_float4(p[0][j], p[1][j], p[2][j], p[3][j]);
            *(float4*)&KP[((tx << 2) + j) * KP_STRIDE + (ty << 2)] = pv;
        }
        __syncthreads();

        // O[i][j] += sum_k P[4ty+i][k] * V[k][4tx+j]
#pragma unroll 8
        for (int k = 0; k < 64; k++) {
            float4 pf = *(float4*)&KP[k * KP_STRIDE + (ty << 2)];
            float4 vf = *(float4*)&Vs[k * 64 + (tx << 2)];
            o[0][0] = fmaf(pf.x, vf.x, o[0][0]); o[0][1] = fmaf(pf.x, vf.y, o[0][1]);
            o[0][2] = fmaf(pf.x, vf.z, o[0][2]); o[0][3] = fmaf(pf.x, vf.w, o[0][3]);
            o[1][0] = fmaf(pf.y, vf.x, o[1][0]); o[1][1] = fmaf(pf.y, vf.y, o[1][1]);
            o[1][2] = fmaf(pf.y, vf.z, o[1][2]); o[1][3] = fmaf(pf.y, vf.w, o[1][3]);
            o[2][0] = fmaf(pf.z, vf.x, o[2][0]); o[2][1] = fmaf(pf.z, vf.y, o[2][1]);
            o[2][2] = fmaf(pf.z, vf.z, o[2][2]); o[2][3] = fmaf(pf.z, vf.w, o[2][3]);
            o[3][0] = fmaf(pf.w, vf.x, o[3][0]); o[3][1] = fmaf(pf.w, vf.y, o[3][1]);
            o[3][2] = fmaf(pf.w, vf.z, o[3][2]); o[3][3] = fmaf(pf.w, vf.w, o[3][3]);
        }
    }

    // Normalize and write to g_ao in [B, N, H*HD] layout (GEMM3 input).
    const int b_ = bh >> 4;
    const int h  = bh & 15;
#pragma unroll
    for (int i = 0; i < 4; i++) {
        int n = qt * 64 + (ty << 2) + i;
        float inv = 1.0f / l_i[i];
        float* p = g_ao + ((size_t)(b_ * SEQ + n)) * DIM + h * HDIM + (tx << 2);
        *(float4*)p = make_float4(o[i][0] * inv, o[i][1] * inv,
                                  o[i][2] * inv, o[i][3] * inv);
    }
}

// ---------------------------------------------------------------------------
// Launch: x, w_qkv, w_proj, b_proj (metadata order). Output fp32 [B,N,D].
// ---------------------------------------------------------------------------
extern "C" void kernel_launch(void* const* d_in, const int* in_sizes, int n_in,
                              void* d_out, int out_size)
{
    (void)in_sizes; (void)n_in; (void)out_size;
    const float* x      = (const float*)d_in[0];
    const float* w_qkv  = (const float*)d_in[1];
    const float* w_proj = (const float*)d_in[2];
    const float* b_proj = (const float*)d_in[3];
    float* out = (float*)d_out;

    // 1) QKV projection + scatter (+Q scale)
    gemm_nt_kernel<0><<<dim3(3072 / 128, MTOT / 128), 256>>>(x, w_qkv, nullptr, nullptr);

    // 2) Flash attention (50 KB dynamic smem -> needs opt-in; idempotent, not a stream op)
    cudaFuncSetAttribute(flash_kernel, cudaFuncAttributeMaxDynamicSharedMemorySize,
                         FLASH_SMEM_BYTES);
    flash_kernel<<<dim3(SEQ / 64, BATCH * NH), 256, FLASH_SMEM_BYTES>>>();

    // 3) Output projection + bias
    gemm_nt_kernel<1><<<dim3(1024 / 128, MTOT / 128), 256>>>(x, w_proj, b_proj, out);
}

// round 8
// speedup vs baseline: 1.3176x; 1.3176x over previous
#include <cuda_runtime.h>
#include <cuda_bf16.h>
#include <cstdint>

// ---------------------------------------------------------------------------
// R7: mma.sync (sm_80 HMMA path — ptxas target is plain sm_103, no tcgen05)
// split-bf16 GEMMs + fp32 flash attention.
//   split: fp32 -> bf16 [hi|lo|hi] (A-side) / [hi|hi|lo] (B-side), K'=3072
//   gemm_mma<0>: qkv = x @ w_qkv^T, scatter Q*scale/K/V fp32
//   flash:       fp32 flash attention, epilogue emits hi/lo/hi bf16 (g_ao2)
//   gemm_mma<1>: out = ao @ w_proj^T + bias
// rel_err ~1e-5 (missing lo*lo term ~2^-17; fp32 accumulate in HMMA).
// ---------------------------------------------------------------------------

#define BATCH  4
#define SEQ    2048
#define DIM    1024
#define NH     16
#define HDIM   64
#define QSCALE 0.125f
#define MTOT   (BATCH * SEQ)     // 8192
#define K3     3072

__device__ float g_q[(size_t)BATCH * NH * SEQ * HDIM];
__device__ float g_k[(size_t)BATCH * NH * SEQ * HDIM];
__device__ float g_v[(size_t)BATCH * NH * SEQ * HDIM];
__device__ __nv_bfloat16 g_xa2[(size_t)MTOT * K3];   // A2 for GEMM1
__device__ __nv_bfloat16 g_wq2[(size_t)3072 * K3];   // B2 for GEMM1
__device__ __nv_bfloat16 g_wp2[(size_t)1024 * K3];   // B2 for GEMM3
__device__ __nv_bfloat16 g_ao2[(size_t)MTOT * K3];   // A2 for GEMM3

// ------------------------------ PTX helpers --------------------------------
__device__ __forceinline__ uint32_t smem_u32(const void* p) {
    uint32_t a;
    asm("{ .reg .u64 t; cvta.to.shared.u64 t, %1; cvt.u32.u64 %0, t; }"
        : "=r"(a) : "l"(p));
    return a;
}
#define CP_ASYNC16(sa, ga) \
    asm volatile("cp.async.cg.shared.global [%0], [%1], 16;" :: "r"(sa), "l"(ga) : "memory")
#define CP_COMMIT() asm volatile("cp.async.commit_group;" ::: "memory")
#define CP_WAIT(n)  asm volatile("cp.async.wait_group %0;" :: "n"(n) : "memory")

#define LDSM_X4(r0, r1, r2, r3, a) \
    asm volatile("ldmatrix.sync.aligned.m8n8.x4.shared.b16 {%0,%1,%2,%3}, [%4];" \
                 : "=r"(r0), "=r"(r1), "=r"(r2), "=r"(r3) : "r"(a))
#define LDSM_X2(r0, r1, a) \
    asm volatile("ldmatrix.sync.aligned.m8n8.x2.shared.b16 {%0,%1}, [%2];" \
                 : "=r"(r0), "=r"(r1) : "r"(a))
#define MMA_BF16(d, a, b) \
    asm volatile("mma.sync.aligned.m16n8k16.row.col.f32.bf16.bf16.f32 " \
                 "{%0,%1,%2,%3}, {%4,%5,%6,%7}, {%8,%9}, {%0,%1,%2,%3};" \
                 : "+f"((d)[0]), "+f"((d)[1]), "+f"((d)[2]), "+f"((d)[3]) \
                 : "r"((a)[0]), "r"((a)[1]), "r"((a)[2]), "r"((a)[3]),   \
                   "r"((b)[0]), "r"((b)[1]))

// ---------------------------------------------------------------------------
// Split fp32 [rows x 1024] -> bf16 [rows x 3072].
// WHICH 0: x -> g_xa2 (hi|lo|hi).  WHICH 1/2: w_qkv/w_proj -> (hi|hi|lo).
// ---------------------------------------------------------------------------
template <int WHICH>
__global__ void split_kernel(const float* __restrict__ src)
{
    __nv_bfloat16* dst = (WHICH == 0) ? g_xa2 : ((WHICH == 1) ? g_wq2 : g_wp2);
    int base = (blockIdx.x * blockDim.x + threadIdx.x) << 2;
    int m = base >> 10, k = base & 1023;
    float4 v = *(const float4*)(src + base);
    __nv_bfloat16 h0 = __float2bfloat16(v.x), h1 = __float2bfloat16(v.y);
    __nv_bfloat16 h2 = __float2bfloat16(v.z), h3 = __float2bfloat16(v.w);
    __nv_bfloat16 l0 = __float2bfloat16(v.x - __bfloat162float(h0));
    __nv_bfloat16 l1 = __float2bfloat16(v.y - __bfloat162float(h1));
    __nv_bfloat16 l2 = __float2bfloat16(v.z - __bfloat162float(h2));
    __nv_bfloat16 l3 = __float2bfloat16(v.w - __bfloat162float(h3));
    __nv_bfloat162 H0, H1, L0, L1;
    H0.x = h0; H0.y = h1; H1.x = h2; H1.y = h3;
    L0.x = l0; L0.y = l1; L1.x = l2; L1.y = l3;
    __nv_bfloat16* d = dst + (size_t)m * K3 + k;
    *(__nv_bfloat162*)(d)     = H0;  *(__nv_bfloat162*)(d + 2)    = H1;
    if (WHICH == 0) {
        *(__nv_bfloat162*)(d + 1024) = L0;  *(__nv_bfloat162*)(d + 1026) = L1;
        *(__nv_bfloat162*)(d + 2048) = H0;  *(__nv_bfloat162*)(d + 2050) = H1;
    } else {
        *(__nv_bfloat162*)(d + 1024) = H0;  *(__nv_bfloat162*)(d + 1026) = H1;
        *(__nv_bfloat162*)(d + 2048) = L0;  *(__nv_bfloat162*)(d + 2050) = L1;
    }
}

// ---------------------------------------------------------------------------
// mma.sync GEMM: C[m,e] = sum_k' A2[m,k'] * B2[e,k']  (both K-contiguous).
// CTA tile 128x128, 8 warps each 64x32 (4 x m16 by 4 x n8 per k16 step).
// K-chunk 64 elems = 128 B/row, SW128 swizzle; 4-stage cp.async ring.
// MODE 0: scatter Q*scale / K / V fp32.  MODE 1: += bias -> Cout.
// ---------------------------------------------------------------------------
#define NITER     48
#define STG_BYTES 32768u                 // A 16 KB + B 16 KB
#define GEMM_DSM  (4 * 32768)

template <int MODE>
__global__ void __launch_bounds__(256)
gemm_mma(const float* __restrict__ bias, float* __restrict__ Cout)
{
    extern __shared__ char dynsm[];
    const uint32_t smb = smem_u32(dynsm);

    const __nv_bfloat16* __restrict__ A2 = (MODE == 0) ? g_xa2 : g_ao2;
    const __nv_bfloat16* __restrict__ B2 = (MODE == 0) ? g_wq2 : g_wp2;

    const int tid  = threadIdx.x;
    const int wid  = tid >> 5, lane = tid & 31;
    const int m0   = blockIdx.y << 7;
    const int e0   = blockIdx.x << 7;
    const int wm   = (wid >> 2) << 6;    // 0 / 64
    const int wn   = (wid & 3) << 5;     // 0 / 32 / 64 / 96

    float d[4][4][4];
#pragma unroll
    for (int mt = 0; mt < 4; mt++)
#pragma unroll
        for (int nt = 0; nt < 4; nt++)
#pragma unroll
            for (int r = 0; r < 4; r++) d[mt][nt][r] = 0.0f;

    // ldmatrix per-lane address components (swizzle: col ^= (row&7)<<4)
    uint32_t offA[4], xorA[4], offB[4], xorB[4];
#pragma unroll
    for (int mt = 0; mt < 4; mt++) {
        int row = wm + mt * 16 + (lane & 15);
        offA[mt] = (uint32_t)row * 128u;
        xorA[mt] = (uint32_t)(row & 7) << 4;
    }
#pragma unroll
    for (int nt = 0; nt < 4; nt++) {
        int row = wn + nt * 8 + (lane & 7);
        offB[nt] = (uint32_t)row * 128u + 16384u;
        xorB[nt] = (uint32_t)(row & 7) << 4;
    }
    const uint32_t hiA = ((uint32_t)(lane >> 4)) * 16u;
    const uint32_t hiB = ((uint32_t)((lane >> 3) & 1)) * 16u;

    auto load_stage = [&](int slot, int it) {
        const uint32_t sA = smb + (uint32_t)slot * STG_BYTES;
        const uint32_t sB = sA + 16384u;
        const __nv_bfloat16* ga = A2 + (size_t)m0 * K3 + it * 64;
        const __nv_bfloat16* gb = B2 + (size_t)e0 * K3 + it * 64;
#pragma unroll
        for (int t = 0; t < 4; t++) {
            int id  = t * 256 + tid;          // 0..1023
            int row = id >> 3, c = id & 7;
            uint32_t so = (uint32_t)row * 128u + (((uint32_t)c * 16u) ^ ((uint32_t)(row & 7) << 4));
            CP_ASYNC16(sA + so, ga + (size_t)row * K3 + c * 8);
            CP_ASYNC16(sB + so, gb + (size_t)row * K3 + c * 8);
        }
    };

#pragma unroll
    for (int p = 0; p < 3; p++) { load_stage(p, p); CP_COMMIT(); }

    for (int i = 0; i < NITER; i++) {
        if (i < NITER - 3) { load_stage((i + 3) & 3, i + 3); CP_COMMIT(); CP_WAIT(2); }
        else if (i == NITER - 3) CP_WAIT(2);
        else if (i == NITER - 2) CP_WAIT(1);
        else                     CP_WAIT(0);
        __syncthreads();

        const uint32_t sS = smb + (uint32_t)(i & 3) * STG_BYTES;
#pragma unroll
        for (int kk = 0; kk < 4; kk++) {
            const uint32_t kba = (uint32_t)kk * 32u + hiA;
            const uint32_t kbb = (uint32_t)kk * 32u + hiB;
            uint32_t a[4][4], b[4][2];
#pragma unroll
            for (int mt = 0; mt < 4; mt++)
                LDSM_X4(a[mt][0], a[mt][1], a[mt][2], a[mt][3],
                        sS + offA[mt] + (kba ^ xorA[mt]));
#pragma unroll
            for (int nt = 0; nt < 4; nt++)
                LDSM_X2(b[nt][0], b[nt][1], sS + offB[nt] + (kbb ^ xorB[nt]));
#pragma unroll
            for (int mt = 0; mt < 4; mt++)
#pragma unroll
                for (int nt = 0; nt < 4; nt++)
                    MMA_BF16(d[mt][nt], a[mt], b[nt]);
        }
        __syncthreads();
    }

    // Epilogue. D frag: (d0,d1)@(row,col..col+1), (d2,d3)@(row+8,col..col+1)
    const int r0 = lane >> 2;
    const int c0 = (lane & 3) << 1;
#pragma unroll
    for (int nt = 0; nt < 4; nt++) {
        const int e = e0 + wn + nt * 8 + c0;
        if (MODE == 0) {
            const int cc  = e >> 10;
            const int h   = (e >> 6) & 15;
            const int hd  = e & 63;
            const float mul = (cc == 0) ? QSCALE : 1.0f;
            float* buf = (cc == 0) ? g_q : ((cc == 1) ? g_k : g_v);
#pragma unroll
            for (int mt = 0; mt < 4; mt++) {
#pragma unroll
                for (int half = 0; half < 2; half++) {
                    int m  = m0 + wm + mt * 16 + r0 + half * 8;
                    int b_ = m >> 11, n = m & 2047;
                    float* p = buf + ((size_t)((b_ * NH + h) * SEQ + n)) * HDIM + hd;
                    *(float2*)p = make_float2(d[mt][nt][2 * half] * mul,
                                              d[mt][nt][2 * half + 1] * mul);
                }
            }
        } else {
            const float2 bv = *(const float2*)(bias + e);
#pragma unroll
            for (int mt = 0; mt < 4; mt++) {
#pragma unroll
                for (int half = 0; half < 2; half++) {
                    int m = m0 + wm + mt * 16 + r0 + half * 8;
                    float* p = Cout + (size_t)m * 1024 + e;
                    *(float2*)p = make_float2(d[mt][nt][2 * half] + bv.x,
                                              d[mt][nt][2 * half + 1] + bv.y);
                }
            }
        }
    }
}

// ---------------------------------------------------------------------------
// Flash attention, fp32 (proven R5 math). Epilogue emits hi/lo/hi bf16 into
// g_ao2 [8192 x 3072] so GEMM3 runs on tensor cores.
// ---------------------------------------------------------------------------
#define KP_STRIDE 68
#define FLASH_SMEM_BYTES ((64 * 64 + 64 * KP_STRIDE + 64 * 64) * 4)

__launch_bounds__(256, 2)
__global__ void flash_kernel()
{
    extern __shared__ float sm[];
    float* QsT = sm;
    float* KP  = sm + 64 * 64;
    float* Vs  = KP + 64 * KP_STRIDE;

    const int tid = threadIdx.x;
    const int ty  = tid >> 4, tx = tid & 15;
    const int qt  = blockIdx.x, bh = blockIdx.y;

    const float* Qg = g_q + (size_t)bh * SEQ * HDIM + (size_t)qt * 64 * HDIM;
    const float* Kg = g_k + (size_t)bh * SEQ * HDIM;
    const float* Vg = g_v + (size_t)bh * SEQ * HDIM;

#pragma unroll
    for (int i = 0; i < 4; i++) {
        int id = tid + i * 256;
        int r = id >> 4, c = (id & 15) << 2;
        float4 q4 = *(const float4*)(Qg + (size_t)r * HDIM + c);
        QsT[(c + 0) * 64 + r] = q4.x;
        QsT[(c + 1) * 64 + r] = q4.y;
        QsT[(c + 2) * 64 + r] = q4.z;
        QsT[(c + 3) * 64 + r] = q4.w;
    }

    float m_i[4], l_i[4], o[4][4];
#pragma unroll
    for (int i = 0; i < 4; i++) {
        m_i[i] = -1e30f; l_i[i] = 0.0f;
#pragma unroll
        for (int j = 0; j < 4; j++) o[i][j] = 0.0f;
    }

    for (int kt = 0; kt < SEQ / 64; kt++) {
        __syncthreads();
        const float* kg = Kg + (size_t)kt * 64 * HDIM;
        const float* vg = Vg + (size_t)kt * 64 * HDIM;
#pragma unroll
        for (int i = 0; i < 4; i++) {
            int id = tid + i * 256;
            int r = id >> 4, c = (id & 15) << 2;
            float4 k4 = *(const float4*)(kg + (size_t)r * HDIM + c);
            KP[(c + 0) * KP_STRIDE + r] = k4.x;
            KP[(c + 1) * KP_STRIDE + r] = k4.y;
            KP[(c + 2) * KP_STRIDE + r] = k4.z;
            KP[(c + 3) * KP_STRIDE + r] = k4.w;
            *(float4*)&Vs[r * 64 + c] = *(const float4*)(vg + (size_t)r * HDIM + c);
        }
        __syncthreads();

        float s[4][4];
#pragma unroll
        for (int i = 0; i < 4; i++)
#pragma unroll
            for (int j = 0; j < 4; j++) s[i][j] = 0.0f;

#pragma unroll 8
        for (int dd = 0; dd < 64; dd++) {
            float4 qf = *(float4*)&QsT[dd * 64 + (ty << 2)];
            float4 kf = *(float4*)&KP [dd * KP_STRIDE + (tx << 2)];
            s[0][0] = fmaf(qf.x, kf.x, s[0][0]); s[0][1] = fmaf(qf.x, kf.y, s[0][1]);
            s[0][2] = fmaf(qf.x, kf.z, s[0][2]); s[0][3] = fmaf(qf.x, kf.w, s[0][3]);
            s[1][0] = fmaf(qf.y, kf.x, s[1][0]); s[1][1] = fmaf(qf.y, kf.y, s[1][1]);
            s[1][2] = fmaf(qf.y, kf.z, s[1][2]); s[1][3] = fmaf(qf.y, kf.w, s[1][3]);
            s[2][0] = fmaf(qf.z, kf.x, s[2][0]); s[2][1] = fmaf(qf.z, kf.y, s[2][1]);
            s[2][2] = fmaf(qf.z, kf.z, s[2][2]); s[2][3] = fmaf(qf.z, kf.w, s[2][3]);
            s[3][0] = fmaf(qf.w, kf.x, s[3][0]); s[3][1] = fmaf(qf.w, kf.y, s[3][1]);
            s[3][2] = fmaf(qf.w, kf.z, s[3][2]); s[3][3] = fmaf(qf.w, kf.w, s[3][3]);
        }

        float p[4][4];
#pragma unroll
        for (int i = 0; i < 4; i++) {
            float mx = fmaxf(fmaxf(s[i][0], s[i][1]), fmaxf(s[i][2], s[i][3]));
#pragma unroll
            for (int w = 8; w >= 1; w >>= 1)
                mx = fmaxf(mx, __shfl_xor_sync(0xffffffffu, mx, w));
            float mnew = fmaxf(m_i[i], mx);
            float corr = __expf(m_i[i] - mnew);
            m_i[i] = mnew;
            float rs = 0.0f;
#pragma unroll
            for (int j = 0; j < 4; j++) { p[i][j] = __expf(s[i][j] - mnew); rs += p[i][j]; }
#pragma unroll
            for (int w = 8; w >= 1; w >>= 1)
                rs += __shfl_xor_sync(0xffffffffu, rs, w);
            l_i[i] = l_i[i] * corr + rs;
#pragma unroll
            for (int j = 0; j < 4; j++) o[i][j] *= corr;
        }

        __syncthreads();
#pragma unroll
        for (int j = 0; j < 4; j++) {
            float4 pv = make_float4(p[0][j], p[1][j], p[2][j], p[3][j]);
            *(float4*)&KP[((tx << 2) + j) * KP_STRIDE + (ty << 2)] = pv;
        }
        __syncthreads();

#pragma unroll 8
        for (int k = 0; k < 64; k++) {
            float4 pf = *(float4*)&KP[k * KP_STRIDE + (ty << 2)];
            float4 vf = *(float4*)&Vs[k * 64 + (tx << 2)];
            o[0][0] = fmaf(pf.x, vf.x, o[0][0]); o[0][1] = fmaf(pf.x, vf.y, o[0][1]);
            o[0][2] = fmaf(pf.x, vf.z, o[0][2]); o[0][3] = fmaf(pf.x, vf.w, o[0][3]);
            o[1][0] = fmaf(pf.y, vf.x, o[1][0]); o[1][1] = fmaf(pf.y, vf.y, o[1][1]);
            o[1][2] = fmaf(pf.y, vf.z, o[1][2]); o[1][3] = fmaf(pf.y, vf.w, o[1][3]);
            o[2][0] = fmaf(pf.z, vf.x, o[2][0]); o[2][1] = fmaf(pf.z, vf.y, o[2][1]);
            o[2][2] = fmaf(pf.z, vf.z, o[2][2]); o[2][3] = fmaf(pf.z, vf.w, o[2][3]);
            o[3][0] = fmaf(pf.w, vf.x, o[3][0]); o[3][1] = fmaf(pf.w, vf.y, o[3][1]);
            o[3][2] = fmaf(pf.w, vf.z, o[3][2]); o[3][3] = fmaf(pf.w, vf.w, o[3][3]);
        }
    }

    // Epilogue: normalize, split hi/lo/hi bf16 into g_ao2 [m][3072].
    const int b_ = bh >> 4;
    const int h  = bh & 15;
    const int kb = h * HDIM + (tx << 2);
#pragma unroll
    for (int i = 0; i < 4; i++) {
        int n = qt * 64 + (ty << 2) + i;
        float inv = 1.0f / l_i[i];
        float v0 = o[i][0] * inv, v1 = o[i][1] * inv;
        float v2 = o[i][2] * inv, v3 = o[i][3] * inv;
        __nv_bfloat16 h0 = __float2bfloat16(v0), h1 = __float2bfloat16(v1);
        __nv_bfloat16 h2 = __float2bfloat16(v2), h3 = __float2bfloat16(v3);
        __nv_bfloat16 l0 = __float2bfloat16(v0 - __bfloat162float(h0));
        __nv_bfloat16 l1 = __float2bfloat16(v1 - __bfloat162float(h1));
        __nv_bfloat16 l2 = __float2bfloat16(v2 - __bfloat162float(h2));
        __nv_bfloat16 l3 = __float2bfloat16(v3 - __bfloat162float(h3));
        __nv_bfloat162 H0, H1, L0, L1;
        H0.x = h0; H0.y = h1; H1.x = h2; H1.y = h3;
        L0.x = l0; L0.y = l1; L1.x = l2; L1.y = l3;
        __nv_bfloat16* base = g_ao2 + (size_t)(b_ * SEQ + n) * K3 + kb;
        *(__nv_bfloat162*)(base)        = H0; *(__nv_bfloat162*)(base + 2)    = H1;
        *(__nv_bfloat162*)(base + 1024) = L0; *(__nv_bfloat162*)(base + 1026) = L1;
        *(__nv_bfloat162*)(base + 2048) = H0; *(__nv_bfloat162*)(base + 2050) = H1;
    }
}

// ---------------------------------------------------------------------------
extern "C" void kernel_launch(void* const* d_in, const int* in_sizes, int n_in,
                              void* d_out, int out_size)
{
    (void)in_sizes; (void)n_in; (void)out_size;
    const float* x      = (const float*)d_in[0];
    const float* w_qkv  = (const float*)d_in[1];
    const float* w_proj = (const float*)d_in[2];
    const float* b_proj = (const float*)d_in[3];
    float* out = (float*)d_out;

    cudaFuncSetAttribute(gemm_mma<0>, cudaFuncAttributeMaxDynamicSharedMemorySize, GEMM_DSM);
    cudaFuncSetAttribute(gemm_mma<1>, cudaFuncAttributeMaxDynamicSharedMemorySize, GEMM_DSM);
    cudaFuncSetAttribute(flash_kernel, cudaFuncAttributeMaxDynamicSharedMemorySize,
                         FLASH_SMEM_BYTES);

    split_kernel<0><<<MTOT * DIM / 4 / 256, 256>>>(x);       // x      -> g_xa2
    split_kernel<1><<<3072 * DIM / 4 / 256, 256>>>(w_qkv);   // w_qkv  -> g_wq2
    split_kernel<2><<<1024 * DIM / 4 / 256, 256>>>(w_proj);  // w_proj -> g_wp2

    gemm_mma<0><<<dim3(3072 / 128, MTOT / 128), 256, GEMM_DSM>>>(nullptr, nullptr);

    flash_kernel<<<dim3(SEQ / 64, BATCH * NH), 256, FLASH_SMEM_BYTES>>>();

    gemm_mma<1><<<dim3(1024 / 128, MTOT / 128), 256, GEMM_DSM>>>(b_proj, out);
}

// round 9
// speedup vs baseline: 3.1224x; 2.3699x over previous
#include <cuda_runtime.h>
#include <cuda_bf16.h>
#include <cstdint>

// ---------------------------------------------------------------------------
// R9: all-tensor-core MHA (legacy mma.sync bf16 with hi/lo split everywhere).
//   split:      x/w_qkv/w_proj fp32 -> bf16 [hi|lo|hi] / [hi|hi|lo], K'=3072
//   gemm_mma<0>: qkv = x @ w_qkv^T -> bf16 hi/lo Q(xscale)/K + V transposed
//   flash_mma:  S=QK^T split-bf16 MMA, online softmax, PV split-bf16 MMA
//               (P frags repacked from S frags in registers), emits g_ao2
//   gemm_mma<1>: out = ao @ w_proj^T + bias
// ---------------------------------------------------------------------------

#define BATCH  4
#define SEQ    2048
#define DIM    1024
#define NH     16
#define HDIM   64
#define QSCALE 0.125f
#define MTOT   (BATCH * SEQ)     // 8192
#define K3     3072
#define BH     (BATCH * NH)      // 64

__device__ __nv_bfloat16 g_qh[(size_t)BH * SEQ * HDIM];   // Q hi  [bh][n][d]
__device__ __nv_bfloat16 g_ql[(size_t)BH * SEQ * HDIM];   // Q lo
__device__ __nv_bfloat16 g_kh[(size_t)BH * SEQ * HDIM];   // K hi
__device__ __nv_bfloat16 g_kl[(size_t)BH * SEQ * HDIM];   // K lo
__device__ __nv_bfloat16 g_vth[(size_t)BH * HDIM * SEQ];  // V^T hi [bh][d][n]
__device__ __nv_bfloat16 g_vtl[(size_t)BH * HDIM * SEQ];  // V^T lo
__device__ __nv_bfloat16 g_xa2[(size_t)MTOT * K3];
__device__ __nv_bfloat16 g_wq2[(size_t)3072 * K3];
__device__ __nv_bfloat16 g_wp2[(size_t)1024 * K3];
__device__ __nv_bfloat16 g_ao2[(size_t)MTOT * K3];

// ------------------------------ PTX helpers --------------------------------
__device__ __forceinline__ uint32_t smem_u32(const void* p) {
    uint32_t a;
    asm("{ .reg .u64 t; cvta.to.shared.u64 t, %1; cvt.u32.u64 %0, t; }"
        : "=r"(a) : "l"(p));
    return a;
}
#define CP_ASYNC16(sa, ga) \
    asm volatile("cp.async.cg.shared.global [%0], [%1], 16;" :: "r"(sa), "l"(ga) : "memory")
#define CP_COMMIT() asm volatile("cp.async.commit_group;" ::: "memory")
#define CP_WAIT(n)  asm volatile("cp.async.wait_group %0;" :: "n"(n) : "memory")

#define LDSM_X4(r0, r1, r2, r3, a) \
    asm volatile("ldmatrix.sync.aligned.m8n8.x4.shared.b16 {%0,%1,%2,%3}, [%4];" \
                 : "=r"(r0), "=r"(r1), "=r"(r2), "=r"(r3) : "r"(a))
#define LDSM_X2(r0, r1, a) \
    asm volatile("ldmatrix.sync.aligned.m8n8.x2.shared.b16 {%0,%1}, [%2];" \
                 : "=r"(r0), "=r"(r1) : "r"(a))
#define MMA_BF16(d, a, b) \
    asm volatile("mma.sync.aligned.m16n8k16.row.col.f32.bf16.bf16.f32 " \
                 "{%0,%1,%2,%3}, {%4,%5,%6,%7}, {%8,%9}, {%0,%1,%2,%3};" \
                 : "+f"((d)[0]), "+f"((d)[1]), "+f"((d)[2]), "+f"((d)[3]) \
                 : "r"((a)[0]), "r"((a)[1]), "r"((a)[2]), "r"((a)[3]),   \
                   "r"((b)[0]), "r"((b)[1]))

__device__ __forceinline__ uint32_t pack_bf2(float x, float y) {
    __nv_bfloat16 bx = __float2bfloat16(x), by = __float2bfloat16(y);
    return ((uint32_t)__bfloat16_as_ushort(by) << 16) | __bfloat16_as_ushort(bx);
}

// ---------------------------------------------------------------------------
// Split fp32 [rows x 1024] -> bf16 [rows x 3072].
// WHICH 0: x -> g_xa2 (hi|lo|hi).  WHICH 1/2: w_qkv/w_proj -> (hi|hi|lo).
// ---------------------------------------------------------------------------
template <int WHICH>
__global__ void split_kernel(const float* __restrict__ src)
{
    __nv_bfloat16* dst = (WHICH == 0) ? g_xa2 : ((WHICH == 1) ? g_wq2 : g_wp2);
    int base = (blockIdx.x * blockDim.x + threadIdx.x) << 2;
    int m = base >> 10, k = base & 1023;
    float4 v = *(const float4*)(src + base);
    __nv_bfloat16 h0 = __float2bfloat16(v.x), h1 = __float2bfloat16(v.y);
    __nv_bfloat16 h2 = __float2bfloat16(v.z), h3 = __float2bfloat16(v.w);
    __nv_bfloat16 l0 = __float2bfloat16(v.x - __bfloat162float(h0));
    __nv_bfloat16 l1 = __float2bfloat16(v.y - __bfloat162float(h1));
    __nv_bfloat16 l2 = __float2bfloat16(v.z - __bfloat162float(h2));
    __nv_bfloat16 l3 = __float2bfloat16(v.w - __bfloat162float(h3));
    __nv_bfloat162 H0, H1, L0, L1;
    H0.x = h0; H0.y = h1; H1.x = h2; H1.y = h3;
    L0.x = l0; L0.y = l1; L1.x = l2; L1.y = l3;
    __nv_bfloat16* d = dst + (size_t)m * K3 + k;
    *(__nv_bfloat162*)(d)     = H0;  *(__nv_bfloat162*)(d + 2)    = H1;
    if (WHICH == 0) {
        *(__nv_bfloat162*)(d + 1024) = L0;  *(__nv_bfloat162*)(d + 1026) = L1;
        *(__nv_bfloat162*)(d + 2048) = H0;  *(__nv_bfloat162*)(d + 2050) = H1;
    } else {
        *(__nv_bfloat162*)(d + 1024) = H0;  *(__nv_bfloat162*)(d + 1026) = H1;
        *(__nv_bfloat162*)(d + 2048) = L0;  *(__nv_bfloat162*)(d + 2050) = L1;
    }
}

// ---------------------------------------------------------------------------
// mma.sync GEMM (R8-proven core, now 3-stage -> 2 CTAs/SM).
// MODE 0: epilogue splits Q(xscale)/K to hi/lo [bh][n][d], V transposed
//         to hi/lo [bh][d][n].
// MODE 1: += bias -> Cout.
// ---------------------------------------------------------------------------
#define NITER     48
#define STG_BYTES 32768u
#define GEMM_DSM  (3 * 32768)

template <int MODE>
__global__ void __launch_bounds__(256)
gemm_mma(const float* __restrict__ bias, float* __restrict__ Cout)
{
    extern __shared__ char dynsm[];
    const uint32_t smb = smem_u32(dynsm);

    const __nv_bfloat16* __restrict__ A2 = (MODE == 0) ? g_xa2 : g_ao2;
    const __nv_bfloat16* __restrict__ B2 = (MODE == 0) ? g_wq2 : g_wp2;

    const int tid  = threadIdx.x;
    const int wid  = tid >> 5, lane = tid & 31;
    const int m0   = blockIdx.y << 7;
    const int e0   = blockIdx.x << 7;
    const int wm   = (wid >> 2) << 6;
    const int wn   = (wid & 3) << 5;

    float d[4][4][4];
#pragma unroll
    for (int mt = 0; mt < 4; mt++)
#pragma unroll
        for (int nt = 0; nt < 4; nt++)
#pragma unroll
            for (int r = 0; r < 4; r++) d[mt][nt][r] = 0.0f;

    uint32_t offA[4], xorA[4], offB[4], xorB[4];
#pragma unroll
    for (int mt = 0; mt < 4; mt++) {
        int row = wm + mt * 16 + (lane & 15);
        offA[mt] = (uint32_t)row * 128u;
        xorA[mt] = (uint32_t)(row & 7) << 4;
    }
#pragma unroll
    for (int nt = 0; nt < 4; nt++) {
        int row = wn + nt * 8 + (lane & 7);
        offB[nt] = (uint32_t)row * 128u + 16384u;
        xorB[nt] = (uint32_t)(row & 7) << 4;
    }
    const uint32_t hiA = ((uint32_t)(lane >> 4)) * 16u;
    const uint32_t hiB = ((uint32_t)((lane >> 3) & 1)) * 16u;

    auto load_stage = [&](int slot, int it) {
        const uint32_t sA = smb + (uint32_t)slot * STG_BYTES;
        const uint32_t sB = sA + 16384u;
        const __nv_bfloat16* ga = A2 + (size_t)m0 * K3 + it * 64;
        const __nv_bfloat16* gb = B2 + (size_t)e0 * K3 + it * 64;
#pragma unroll
        for (int t = 0; t < 4; t++) {
            int id  = t * 256 + tid;
            int row = id >> 3, c = id & 7;
            uint32_t so = (uint32_t)row * 128u + (((uint32_t)c * 16u) ^ ((uint32_t)(row & 7) << 4));
            CP_ASYNC16(sA + so, ga + (size_t)row * K3 + c * 8);
            CP_ASYNC16(sB + so, gb + (size_t)row * K3 + c * 8);
        }
    };

    load_stage(0, 0); CP_COMMIT();
    load_stage(1, 1); CP_COMMIT();

    for (int i = 0; i < NITER; i++) {
        if (i + 2 < NITER)      { load_stage((i + 2) % 3, i + 2); CP_COMMIT(); CP_WAIT(2); }
        else if (i + 2 == NITER)  CP_WAIT(1);
        else                      CP_WAIT(0);
        __syncthreads();

        const uint32_t sS = smb + (uint32_t)(i % 3) * STG_BYTES;
#pragma unroll
        for (int kk = 0; kk < 4; kk++) {
            const uint32_t kba = (uint32_t)kk * 32u + hiA;
            const uint32_t kbb = (uint32_t)kk * 32u + hiB;
            uint32_t a[4][4], b[4][2];
#pragma unroll
            for (int mt = 0; mt < 4; mt++)
                LDSM_X4(a[mt][0], a[mt][1], a[mt][2], a[mt][3],
                        sS + offA[mt] + (kba ^ xorA[mt]));
#pragma unroll
            for (int nt = 0; nt < 4; nt++)
                LDSM_X2(b[nt][0], b[nt][1], sS + offB[nt] + (kbb ^ xorB[nt]));
#pragma unroll
            for (int mt = 0; mt < 4; mt++)
#pragma unroll
                for (int nt = 0; nt < 4; nt++)
                    MMA_BF16(d[mt][nt], a[mt], b[nt]);
        }
        __syncthreads();
    }

    const int r0 = lane >> 2;
    const int c0 = (lane & 3) << 1;
#pragma unroll
    for (int nt = 0; nt < 4; nt++) {
        const int e = e0 + wn + nt * 8 + c0;
        if (MODE == 0) {
            const int cc = e >> 10;
            const int h  = (e >> 6) & 15;
            const int hd = e & 63;
            const float mul = (cc == 0) ? QSCALE : 1.0f;
#pragma unroll
            for (int mt = 0; mt < 4; mt++) {
#pragma unroll
                for (int half = 0; half < 2; half++) {
                    int m  = m0 + wm + mt * 16 + r0 + half * 8;
                    int b_ = m >> 11, n = m & 2047;
                    int bh = b_ * NH + h;
                    float v0 = d[mt][nt][2 * half] * mul;
                    float v1 = d[mt][nt][2 * half + 1] * mul;
                    __nv_bfloat16 h0 = __float2bfloat16(v0);
                    __nv_bfloat16 h1 = __float2bfloat16(v1);
                    __nv_bfloat16 l0 = __float2bfloat16(v0 - __bfloat162float(h0));
                    __nv_bfloat16 l1 = __float2bfloat16(v1 - __bfloat162float(h1));
                    if (cc == 2) {            // V transposed [bh][d][n]
                        size_t base = ((size_t)bh * HDIM + hd) * SEQ + n;
                        g_vth[base]       = h0;  g_vth[base + SEQ] = h1;
                        g_vtl[base]       = l0;  g_vtl[base + SEQ] = l1;
                    } else {
                        __nv_bfloat16* BHp = cc ? g_kh : g_qh;
                        __nv_bfloat16* BLp = cc ? g_kl : g_ql;
                        size_t base = ((size_t)bh * SEQ + n) * HDIM + hd;
                        __nv_bfloat162 Hp, Lp;
                        Hp.x = h0; Hp.y = h1; Lp.x = l0; Lp.y = l1;
                        *(__nv_bfloat162*)&BHp[base] = Hp;
                        *(__nv_bfloat162*)&BLp[base] = Lp;
                    }
                }
            }
        } else {
            const float2 bv = *(const float2*)(bias + e);
#pragma unroll
            for (int mt = 0; mt < 4; mt++) {
#pragma unroll
                for (int half = 0; half < 2; half++) {
                    int m = m0 + wm + mt * 16 + r0 + half * 8;
                    float* p = Cout + (size_t)m * 1024 + e;
                    *(float2*)p = make_float2(d[mt][nt][2 * half] + bv.x,
                                              d[mt][nt][2 * half + 1] + bv.y);
                }
            }
        }
    }
}

// ---------------------------------------------------------------------------
// Flash attention on mma.sync. Grid (16 q-tiles, 64 bh), 256 thr (8 warps x
// 16 q-rows). S = Q K^T with [qh,ql,qh]x[kh,kh,kl]; online softmax in frags;
// PV with P repacked from S frags ([ph,pl,ph]x[vh,vh,vl], V pre-transposed).
// Epilogue: /l, split hi/lo/hi bf16 -> g_ao2.
// Smem: Qh 16K | Ql 16K | 2 stages x (Kh 8K | Kl 8K | Vth 8K | Vtl 8K).
// ---------------------------------------------------------------------------
#define FL_DSM (32768 + 2 * 32768)

__global__ void __launch_bounds__(256)
flash_mma()
{
    extern __shared__ char fsm[];
    const uint32_t smb = smem_u32(fsm);
    const uint32_t Qh = smb, Ql = smb + 16384u;

    const int tid  = threadIdx.x;
    const int wid  = tid >> 5, lane = tid & 31;
    const int qt   = blockIdx.x;           // 0..15
    const int bh   = blockIdx.y;           // 0..63
    const int wm   = wid << 4;             // 16 q-rows per warp

    const __nv_bfloat16* Qhg = g_qh + ((size_t)bh * SEQ + qt * 128) * HDIM;
    const __nv_bfloat16* Qlg = g_ql + ((size_t)bh * SEQ + qt * 128) * HDIM;
    const __nv_bfloat16* Khg = g_kh + (size_t)bh * SEQ * HDIM;
    const __nv_bfloat16* Klg = g_kl + (size_t)bh * SEQ * HDIM;
    const __nv_bfloat16* Vthg = g_vth + (size_t)bh * HDIM * SEQ;
    const __nv_bfloat16* Vtlg = g_vtl + (size_t)bh * HDIM * SEQ;

    // Q tiles: 128 rows x 8 chunks, hi+lo
#pragma unroll
    for (int t = 0; t < 4; t++) {
        int id = t * 256 + tid;
        int row = id >> 3, c = id & 7;
        uint32_t so = (uint32_t)row * 128u + (((uint32_t)c * 16u) ^ ((uint32_t)(row & 7) << 4));
        CP_ASYNC16(Qh + so, Qhg + (size_t)row * HDIM + c * 8);
        CP_ASYNC16(Ql + so, Qlg + (size_t)row * HDIM + c * 8);
    }

    auto load_kv = [&](int slot, int kt) {
        const uint32_t st = smb + 32768u + (uint32_t)slot * 32768u;
#pragma unroll
        for (int t = 0; t < 2; t++) {
            int id = t * 256 + tid;        // 0..511 -> 64 rows x 8 chunks
            int row = id >> 3, c = id & 7;
            uint32_t so = (uint32_t)row * 128u + (((uint32_t)c * 16u) ^ ((uint32_t)(row & 7) << 4));
            CP_ASYNC16(st + so,          Khg + (size_t)(kt * 64 + row) * HDIM + c * 8);
            CP_ASYNC16(st + 8192u + so,  Klg + (size_t)(kt * 64 + row) * HDIM + c * 8);
            CP_ASYNC16(st + 16384u + so, Vthg + (size_t)row * SEQ + kt * 64 + c * 8);
            CP_ASYNC16(st + 24576u + so, Vtlg + (size_t)row * SEQ + kt * 64 + c * 8);
        }
    };

    load_kv(0, 0);
    CP_COMMIT();

    // ldmatrix address components
    const uint32_t rA   = (uint32_t)(wm + (lane & 15));
    const uint32_t offA = rA * 128u;
    const uint32_t xorA = (rA & 7u) << 4;
    const uint32_t hiA  = ((uint32_t)(lane >> 4)) * 16u;
    const uint32_t offBk = (uint32_t)(lane & 7) * 128u;
    const uint32_t xorB  = (uint32_t)(lane & 7) << 4;
    const uint32_t hiB   = ((uint32_t)((lane >> 3) & 1)) * 16u;

    float m_[2] = {-1e30f, -1e30f}, l_[2] = {0.0f, 0.0f};
    float of[8][4];
#pragma unroll
    for (int nt = 0; nt < 8; nt++)
#pragma unroll
        for (int r = 0; r < 4; r++) of[nt][r] = 0.0f;

    for (int it = 0; it < SEQ / 64; it++) {
        if (it + 1 < SEQ / 64) { load_kv((it + 1) & 1, it + 1); CP_COMMIT(); CP_WAIT(1); }
        else                     CP_WAIT(0);
        __syncthreads();

        const uint32_t st  = smb + 32768u + (uint32_t)(it & 1) * 32768u;
        const uint32_t KH = st, KL = st + 8192u, VTH = st + 16384u, VTL = st + 24576u;

        // ---- S = Q K^T (3-way split over d) ----
        float sf[8][4];
#pragma unroll
        for (int nt = 0; nt < 8; nt++)
#pragma unroll
            for (int r = 0; r < 4; r++) sf[nt][r] = 0.0f;

#pragma unroll
        for (int k16 = 0; k16 < 4; k16++) {
            const uint32_t kb = (uint32_t)k16 * 32u;
            uint32_t a[4], b[8][2];
#pragma unroll
            for (int nt = 0; nt < 8; nt++)
                LDSM_X2(b[nt][0], b[nt][1], KH + (uint32_t)nt * 1024u + offBk + ((kb + hiB) ^ xorB));
            LDSM_X4(a[0], a[1], a[2], a[3], Qh + offA + ((kb + hiA) ^ xorA));
#pragma unroll
            for (int nt = 0; nt < 8; nt++) MMA_BF16(sf[nt], a, b[nt]);
            LDSM_X4(a[0], a[1], a[2], a[3], Ql + offA + ((kb + hiA) ^ xorA));
#pragma unroll
            for (int nt = 0; nt < 8; nt++) MMA_BF16(sf[nt], a, b[nt]);
#pragma unroll
            for (int nt = 0; nt < 8; nt++)
                LDSM_X2(b[nt][0], b[nt][1], KL + (uint32_t)nt * 1024u + offBk + ((kb + hiB) ^ xorB));
            LDSM_X4(a[0], a[1], a[2], a[3], Qh + offA + ((kb + hiA) ^ xorA));
#pragma unroll
            for (int nt = 0; nt < 8; nt++) MMA_BF16(sf[nt], a, b[nt]);
        }

        // ---- online softmax (rows r=lane>>2 and r+8; quad reductions) ----
        uint32_t ph[2][8], pl[2][8];
#pragma unroll
        for (int i = 0; i < 2; i++) {
            float mx = -1e30f;
#pragma unroll
            for (int nt = 0; nt < 8; nt++)
                mx = fmaxf(mx, fmaxf(sf[nt][2 * i], sf[nt][2 * i + 1]));
            mx = fmaxf(mx, __shfl_xor_sync(0xffffffffu, mx, 1));
            mx = fmaxf(mx, __shfl_xor_sync(0xffffffffu, mx, 2));
            float mnew = fmaxf(m_[i], mx);
            float corr = __expf(m_[i] - mnew);
            m_[i] = mnew;
            float rs = 0.0f;
#pragma unroll
            for (int nt = 0; nt < 8; nt++) {
                float p0 = __expf(sf[nt][2 * i]     - mnew);
                float p1 = __expf(sf[nt][2 * i + 1] - mnew);
                rs += p0 + p1;
                __nv_bfloat16 h0 = __float2bfloat16(p0), h1 = __float2bfloat16(p1);
                float f0 = __bfloat162float(h0), f1 = __bfloat162float(h1);
                ph[i][nt] = ((uint32_t)__bfloat16_as_ushort(h1) << 16) | __bfloat16_as_ushort(h0);
                pl[i][nt] = pack_bf2(p0 - f0, p1 - f1);
            }
            rs += __shfl_xor_sync(0xffffffffu, rs, 1);
            rs += __shfl_xor_sync(0xffffffffu, rs, 2);
            l_[i] = l_[i] * corr + rs;
#pragma unroll
            for (int nt = 0; nt < 8; nt++) {
                of[nt][2 * i]     *= corr;
                of[nt][2 * i + 1] *= corr;
            }
        }

        // ---- PV: O += P V  (3-way split over kv; P frags from registers) ----
#pragma unroll
        for (int g = 0; g < 4; g++) {
            uint32_t ah[4] = { ph[0][2 * g], ph[1][2 * g], ph[0][2 * g + 1], ph[1][2 * g + 1] };
            uint32_t al[4] = { pl[0][2 * g], pl[1][2 * g], pl[0][2 * g + 1], pl[1][2 * g + 1] };
            const uint32_t kb = (uint32_t)g * 32u;
            uint32_t b[8][2];
#pragma unroll
            for (int nt = 0; nt < 8; nt++)
                LDSM_X2(b[nt][0], b[nt][1], VTH + (uint32_t)nt * 1024u + offBk + ((kb + hiB) ^ xorB));
#pragma unroll
            for (int nt = 0; nt < 8; nt++) MMA_BF16(of[nt], ah, b[nt]);
#pragma unroll
            for (int nt = 0; nt < 8; nt++) MMA_BF16(of[nt], al, b[nt]);
#pragma unroll
            for (int nt = 0; nt < 8; nt++)
                LDSM_X2(b[nt][0], b[nt][1], VTL + (uint32_t)nt * 1024u + offBk + ((kb + hiB) ^ xorB));
#pragma unroll
            for (int nt = 0; nt < 8; nt++) MMA_BF16(of[nt], ah, b[nt]);
        }
        __syncthreads();   // all warps done with this stage before it's reloaded
    }

    // ---- epilogue: normalize, split hi/lo/hi -> g_ao2 [8192][3072] ----
    const float inv0 = 1.0f / l_[0], inv1 = 1.0f / l_[1];
    const int r = lane >> 2, c0 = (lane & 3) << 1;
    const int b_ = bh >> 4, h = bh & 15;
#pragma unroll
    for (int nt = 0; nt < 8; nt++) {
#pragma unroll
        for (int i = 0; i < 2; i++) {
            float inv = i ? inv1 : inv0;
            int n = qt * 128 + wm + r + i * 8;
            float v0 = of[nt][2 * i] * inv, v1 = of[nt][2 * i + 1] * inv;
            __nv_bfloat16 h0 = __float2bfloat16(v0), h1 = __float2bfloat16(v1);
            uint32_t Hp = ((uint32_t)__bfloat16_as_ushort(h1) << 16) | __bfloat16_as_ushort(h0);
            uint32_t Lp = pack_bf2(v0 - __bfloat162float(h0), v1 - __bfloat162float(h1));
            __nv_bfloat16* base = g_ao2 + ((size_t)(b_ * SEQ + n)) * K3 + h * HDIM + nt * 8 + c0;
            *(uint32_t*)(base)        = Hp;
            *(uint32_t*)(base + 1024) = Lp;
            *(uint32_t*)(base + 2048) = Hp;
        }
    }
}

// ---------------------------------------------------------------------------
extern "C" void kernel_launch(void* const* d_in, const int* in_sizes, int n_in,
                              void* d_out, int out_size)
{
    (void)in_sizes; (void)n_in; (void)out_size;
    const float* x      = (const float*)d_in[0];
    const float* w_qkv  = (const float*)d_in[1];
    const float* w_proj = (const float*)d_in[2];
    const float* b_proj = (const float*)d_in[3];
    float* out = (float*)d_out;

    cudaFuncSetAttribute(gemm_mma<0>, cudaFuncAttributeMaxDynamicSharedMemorySize, GEMM_DSM);
    cudaFuncSetAttribute(gemm_mma<1>, cudaFuncAttributeMaxDynamicSharedMemorySize, GEMM_DSM);
    cudaFuncSetAttribute(flash_mma, cudaFuncAttributeMaxDynamicSharedMemorySize, FL_DSM);

    split_kernel<0><<<MTOT * DIM / 4 / 256, 256>>>(x);
    split_kernel<1><<<3072 * DIM / 4 / 256, 256>>>(w_qkv);
    split_kernel<2><<<1024 * DIM / 4 / 256, 256>>>(w_proj);

    gemm_mma<0><<<dim3(3072 / 128, MTOT / 128), 256, GEMM_DSM>>>(nullptr, nullptr);

    flash_mma<<<dim3(SEQ / 128, BH), 256, FL_DSM>>>();

    gemm_mma<1><<<dim3(1024 / 128, MTOT / 128), 256, GEMM_DSM>>>(b_proj, out);
}

// round 10
// speedup vs baseline: 4.4640x; 1.4297x over previous
#include <cuda_runtime.h>
#include <cuda_fp16.h>
#include <cstdint>

// ---------------------------------------------------------------------------
// R10: fp16 2-term split everywhere (11-bit mantissa: [ah,al]x[bh,bh] gives
// a*bh exactly; only a*bl ~2^-12 dropped), all matmuls on mma.sync f16.
//   split:      x -> [hi|lo] fp16 (K'=2048); w_qkv/w_proj -> fp16 cast
//   gemm_mma<0>: qkv = x @ w_qkv^T -> Q hi/lo (xscale), K hi, V^T hi
//   flash_mma:  S=[qh,ql]x[kh,kh]; online softmax; PV=[ph,pl]x[vh,vh]
//   gemm_mma<1>: out = ao @ w_proj^T + bias
// ---------------------------------------------------------------------------

#define BATCH  4
#define SEQ    2048
#define DIM    1024
#define NH     16
#define HDIM   64
#define QSCALE 0.125f
#define MTOT   (BATCH * SEQ)     // 8192
#define K2     2048
#define BH     (BATCH * NH)      // 64

__device__ __half g_x2[(size_t)MTOT * K2];        // x  [m][hi|lo]    32 MB
__device__ __half g_w1[(size_t)3072 * 1024];      // w_qkv hi          6 MB
__device__ __half g_w3[(size_t)1024 * 1024];      // w_proj hi         2 MB
__device__ __half g_ao[(size_t)MTOT * K2];        // attn out [hi|lo] 32 MB
__device__ __half g_qh[(size_t)BH * SEQ * HDIM];  // Q hi (scaled)
__device__ __half g_ql[(size_t)BH * SEQ * HDIM];  // Q lo
__device__ __half g_kh[(size_t)BH * SEQ * HDIM];  // K hi
__device__ __half g_vth[(size_t)BH * HDIM * SEQ]; // V^T hi [bh][d][n]

// ------------------------------ PTX helpers --------------------------------
__device__ __forceinline__ uint32_t smem_u32(const void* p) {
    uint32_t a;
    asm("{ .reg .u64 t; cvta.to.shared.u64 t, %1; cvt.u32.u64 %0, t; }"
        : "=r"(a) : "l"(p));
    return a;
}
#define CP_ASYNC16(sa, ga) \
    asm volatile("cp.async.cg.shared.global [%0], [%1], 16;" :: "r"(sa), "l"(ga) : "memory")
#define CP_COMMIT() asm volatile("cp.async.commit_group;" ::: "memory")
#define CP_WAIT(n)  asm volatile("cp.async.wait_group %0;" :: "n"(n) : "memory")

#define LDSM_X4(r0, r1, r2, r3, a) \
    asm volatile("ldmatrix.sync.aligned.m8n8.x4.shared.b16 {%0,%1,%2,%3}, [%4];" \
                 : "=r"(r0), "=r"(r1), "=r"(r2), "=r"(r3) : "r"(a))
#define LDSM_X2(r0, r1, a) \
    asm volatile("ldmatrix.sync.aligned.m8n8.x2.shared.b16 {%0,%1}, [%2];" \
                 : "=r"(r0), "=r"(r1) : "r"(a))
#define MMA_F16(d, a, b) \
    asm volatile("mma.sync.aligned.m16n8k16.row.col.f32.f16.f16.f32 " \
                 "{%0,%1,%2,%3}, {%4,%5,%6,%7}, {%8,%9}, {%0,%1,%2,%3};" \
                 : "+f"((d)[0]), "+f"((d)[1]), "+f"((d)[2]), "+f"((d)[3]) \
                 : "r"((a)[0]), "r"((a)[1]), "r"((a)[2]), "r"((a)[3]),   \
                   "r"((b)[0]), "r"((b)[1]))

__device__ __forceinline__ uint32_t pack_h2(float x, float y) {
    __half hx = __float2half(x), hy = __float2half(y);
    return ((uint32_t)__half_as_ushort(hy) << 16) | __half_as_ushort(hx);
}

// ---------------------------------------------------------------------------
// Splits. x -> g_x2 [m][2048] = hi|lo.  w -> plain fp16 cast.
// ---------------------------------------------------------------------------
__global__ void split_x(const float* __restrict__ src)
{
    int base = (blockIdx.x * blockDim.x + threadIdx.x) << 2;
    int m = base >> 10, k = base & 1023;
    float4 v = *(const float4*)(src + base);
    __half h0 = __float2half(v.x), h1 = __float2half(v.y);
    __half h2 = __float2half(v.z), h3 = __float2half(v.w);
    __half l0 = __float2half(v.x - __half2float(h0));
    __half l1 = __float2half(v.y - __half2float(h1));
    __half l2 = __float2half(v.z - __half2float(h2));
    __half l3 = __float2half(v.w - __half2float(h3));
    __half2 H0, H1, L0, L1;
    H0.x = h0; H0.y = h1; H1.x = h2; H1.y = h3;
    L0.x = l0; L0.y = l1; L1.x = l2; L1.y = l3;
    __half* d = g_x2 + (size_t)m * K2 + k;
    *(__half2*)(d)        = H0;  *(__half2*)(d + 2)    = H1;
    *(__half2*)(d + 1024) = L0;  *(__half2*)(d + 1026) = L1;
}

template <int W>
__global__ void cast_w(const float* __restrict__ src)
{
    __half* dst = W ? g_w3 : g_w1;
    int base = (blockIdx.x * blockDim.x + threadIdx.x) << 2;
    float4 v = *(const float4*)(src + base);
    __half2 H0, H1;
    H0.x = __float2half(v.x); H0.y = __float2half(v.y);
    H1.x = __float2half(v.z); H1.y = __float2half(v.w);
    *(__half2*)(dst + base)     = H0;
    *(__half2*)(dst + base + 2) = H1;
}

// ---------------------------------------------------------------------------
// mma.sync GEMM: C[m,e] = sum_{it<32} A2[m, it*64+j] * B[e, (it&15)*64+j].
// A2 [m][2048] (hi|lo), B [e][1024] (hi), so C = (a_hi+a_lo)*b_hi exactly.
// 128x128 tile, 8 warps x (64x32), 3-stage cp.async.
// MODE 0: epilogue -> Q hi/lo (xscale), K hi, V^T hi.  MODE 1: += bias.
// ---------------------------------------------------------------------------
#define NITER     32
#define STG_BYTES 32768u
#define GEMM_DSM  (3 * 32768)

template <int MODE>
__global__ void __launch_bounds__(256)
gemm_mma(const float* __restrict__ bias, float* __restrict__ Cout)
{
    extern __shared__ char dynsm[];
    const uint32_t smb = smem_u32(dynsm);

    const __half* __restrict__ A2 = (MODE == 0) ? g_x2 : g_ao;
    const __half* __restrict__ B2 = (MODE == 0) ? g_w1 : g_w3;

    const int tid  = threadIdx.x;
    const int wid  = tid >> 5, lane = tid & 31;
    const int m0   = blockIdx.y << 7;
    const int e0   = blockIdx.x << 7;
    const int wm   = (wid >> 2) << 6;
    const int wn   = (wid & 3) << 5;

    float d[4][4][4];
#pragma unroll
    for (int mt = 0; mt < 4; mt++)
#pragma unroll
        for (int nt = 0; nt < 4; nt++)
#pragma unroll
            for (int r = 0; r < 4; r++) d[mt][nt][r] = 0.0f;

    uint32_t offA[4], xorA[4], offB[4], xorB[4];
#pragma unroll
    for (int mt = 0; mt < 4; mt++) {
        int row = wm + mt * 16 + (lane & 15);
        offA[mt] = (uint32_t)row * 128u;
        xorA[mt] = (uint32_t)(row & 7) << 4;
    }
#pragma unroll
    for (int nt = 0; nt < 4; nt++) {
        int row = wn + nt * 8 + (lane & 7);
        offB[nt] = (uint32_t)row * 128u + 16384u;
        xorB[nt] = (uint32_t)(row & 7) << 4;
    }
    const uint32_t hiA = ((uint32_t)(lane >> 4)) * 16u;
    const uint32_t hiB = ((uint32_t)((lane >> 3) & 1)) * 16u;

    auto load_stage = [&](int slot, int it) {
        const uint32_t sA = smb + (uint32_t)slot * STG_BYTES;
        const uint32_t sB = sA + 16384u;
        const __half* ga = A2 + (size_t)m0 * K2 + it * 64;
        const __half* gb = B2 + (size_t)e0 * 1024 + (it & 15) * 64;
#pragma unroll
        for (int t = 0; t < 4; t++) {
            int id  = t * 256 + tid;
            int row = id >> 3, c = id & 7;
            uint32_t so = (uint32_t)row * 128u + (((uint32_t)c * 16u) ^ ((uint32_t)(row & 7) << 4));
            CP_ASYNC16(sA + so, ga + (size_t)row * K2 + c * 8);
            CP_ASYNC16(sB + so, gb + (size_t)row * 1024 + c * 8);
        }
    };

    load_stage(0, 0); CP_COMMIT();
    load_stage(1, 1); CP_COMMIT();

    for (int i = 0; i < NITER; i++) {
        if (i + 2 < NITER)      { load_stage((i + 2) % 3, i + 2); CP_COMMIT(); CP_WAIT(2); }
        else if (i + 2 == NITER)  CP_WAIT(1);
        else                      CP_WAIT(0);
        __syncthreads();

        const uint32_t sS = smb + (uint32_t)(i % 3) * STG_BYTES;
#pragma unroll
        for (int kk = 0; kk < 4; kk++) {
            const uint32_t kba = (uint32_t)kk * 32u + hiA;
            const uint32_t kbb = (uint32_t)kk * 32u + hiB;
            uint32_t a[4][4], b[4][2];
#pragma unroll
            for (int mt = 0; mt < 4; mt++)
                LDSM_X4(a[mt][0], a[mt][1], a[mt][2], a[mt][3],
                        sS + offA[mt] + (kba ^ xorA[mt]));
#pragma unroll
            for (int nt = 0; nt < 4; nt++)
                LDSM_X2(b[nt][0], b[nt][1], sS + offB[nt] + (kbb ^ xorB[nt]));
#pragma unroll
            for (int mt = 0; mt < 4; mt++)
#pragma unroll
                for (int nt = 0; nt < 4; nt++)
                    MMA_F16(d[mt][nt], a[mt], b[nt]);
        }
        __syncthreads();
    }

    const int r0 = lane >> 2;
    const int c0 = (lane & 3) << 1;
#pragma unroll
    for (int nt = 0; nt < 4; nt++) {
        const int e = e0 + wn + nt * 8 + c0;
        if (MODE == 0) {
            const int cc = e >> 10;
            const int h  = (e >> 6) & 15;
            const int hd = e & 63;
            const float mul = (cc == 0) ? QSCALE : 1.0f;
#pragma unroll
            for (int mt = 0; mt < 4; mt++) {
#pragma unroll
                for (int half = 0; half < 2; half++) {
                    int m  = m0 + wm + mt * 16 + r0 + half * 8;
                    int b_ = m >> 11, n = m & 2047;
                    int bh = b_ * NH + h;
                    float v0 = d[mt][nt][2 * half] * mul;
                    float v1 = d[mt][nt][2 * half + 1] * mul;
                    __half h0 = __float2half(v0), h1 = __float2half(v1);
                    if (cc == 0) {
                        __half l0 = __float2half(v0 - __half2float(h0));
                        __half l1 = __float2half(v1 - __half2float(h1));
                        size_t base = ((size_t)bh * SEQ + n) * HDIM + hd;
                        __half2 Hp, Lp;
                        Hp.x = h0; Hp.y = h1; Lp.x = l0; Lp.y = l1;
                        *(__half2*)&g_qh[base] = Hp;
                        *(__half2*)&g_ql[base] = Lp;
                    } else if (cc == 1) {
                        size_t base = ((size_t)bh * SEQ + n) * HDIM + hd;
                        __half2 Hp; Hp.x = h0; Hp.y = h1;
                        *(__half2*)&g_kh[base] = Hp;
                    } else {                 // V transposed [bh][d][n]
                        size_t base = ((size_t)bh * HDIM + hd) * SEQ + n;
                        g_vth[base]       = h0;
                        g_vth[base + SEQ] = h1;
                    }
                }
            }
        } else {
            const float2 bv = *(const float2*)(bias + e);
#pragma unroll
            for (int mt = 0; mt < 4; mt++) {
#pragma unroll
                for (int half = 0; half < 2; half++) {
                    int m = m0 + wm + mt * 16 + r0 + half * 8;
                    float* p = Cout + (size_t)m * 1024 + e;
                    *(float2*)p = make_float2(d[mt][nt][2 * half] + bv.x,
                                              d[mt][nt][2 * half + 1] + bv.y);
                }
            }
        }
    }
}

// ---------------------------------------------------------------------------
// Flash attention, fp16 2-term. Grid (16 q-tiles, 64 bh), 256 thr.
// S = (qh+ql) kh; online softmax; PV = (ph+pl) vh (P frags from registers).
// Smem: Qh 16K | Ql 16K | 2 stages x (Kh 8K | Vth 8K) = 64 KB.
// ---------------------------------------------------------------------------
#define FL_DSM (32768 + 2 * 16384)

__global__ void __launch_bounds__(256)
flash_mma()
{
    extern __shared__ char fsm[];
    const uint32_t smb = smem_u32(fsm);
    const uint32_t Qh = smb, Ql = smb + 16384u;

    const int tid  = threadIdx.x;
    const int wid  = tid >> 5, lane = tid & 31;
    const int qt   = blockIdx.x;
    const int bh   = blockIdx.y;
    const int wm   = wid << 4;

    const __half* Qhg  = g_qh + ((size_t)bh * SEQ + qt * 128) * HDIM;
    const __half* Qlg  = g_ql + ((size_t)bh * SEQ + qt * 128) * HDIM;
    const __half* Khg  = g_kh + (size_t)bh * SEQ * HDIM;
    const __half* Vthg = g_vth + (size_t)bh * HDIM * SEQ;

#pragma unroll
    for (int t = 0; t < 4; t++) {
        int id = t * 256 + tid;
        int row = id >> 3, c = id & 7;
        uint32_t so = (uint32_t)row * 128u + (((uint32_t)c * 16u) ^ ((uint32_t)(row & 7) << 4));
        CP_ASYNC16(Qh + so, Qhg + (size_t)row * HDIM + c * 8);
        CP_ASYNC16(Ql + so, Qlg + (size_t)row * HDIM + c * 8);
    }

    auto load_kv = [&](int slot, int kt) {
        const uint32_t st = smb + 32768u + (uint32_t)slot * 16384u;
#pragma unroll
        for (int t = 0; t < 2; t++) {
            int id = t * 256 + tid;        // 64 rows x 8 chunks
            int row = id >> 3, c = id & 7;
            uint32_t so = (uint32_t)row * 128u + (((uint32_t)c * 16u) ^ ((uint32_t)(row & 7) << 4));
            CP_ASYNC16(st + so,         Khg + (size_t)(kt * 64 + row) * HDIM + c * 8);
            CP_ASYNC16(st + 8192u + so, Vthg + (size_t)row * SEQ + kt * 64 + c * 8);
        }
    };

    load_kv(0, 0);
    CP_COMMIT();

    const uint32_t rA   = (uint32_t)(wm + (lane & 15));
    const uint32_t offA = rA * 128u;
    const uint32_t xorA = (rA & 7u) << 4;
    const uint32_t hiA  = ((uint32_t)(lane >> 4)) * 16u;
    const uint32_t offBk = (uint32_t)(lane & 7) * 128u;
    const uint32_t xorB  = (uint32_t)(lane & 7) << 4;
    const uint32_t hiB   = ((uint32_t)((lane >> 3) & 1)) * 16u;

    float m_[2] = {-1e30f, -1e30f}, l_[2] = {0.0f, 0.0f};
    float of[8][4];
#pragma unroll
    for (int nt = 0; nt < 8; nt++)
#pragma unroll
        for (int r = 0; r < 4; r++) of[nt][r] = 0.0f;

    for (int it = 0; it < SEQ / 64; it++) {
        if (it + 1 < SEQ / 64) { load_kv((it + 1) & 1, it + 1); CP_COMMIT(); CP_WAIT(1); }
        else                     CP_WAIT(0);
        __syncthreads();

        const uint32_t st  = smb + 32768u + (uint32_t)(it & 1) * 16384u;
        const uint32_t KH = st, VTH = st + 8192u;

        // ---- S = (qh+ql) kh ----
        float sf[8][4];
#pragma unroll
        for (int nt = 0; nt < 8; nt++)
#pragma unroll
            for (int r = 0; r < 4; r++) sf[nt][r] = 0.0f;

#pragma unroll
        for (int k16 = 0; k16 < 4; k16++) {
            const uint32_t kb = (uint32_t)k16 * 32u;
            uint32_t a[4], b[8][2];
#pragma unroll
            for (int nt = 0; nt < 8; nt++)
                LDSM_X2(b[nt][0], b[nt][1], KH + (uint32_t)nt * 1024u + offBk + ((kb + hiB) ^ xorB));
            LDSM_X4(a[0], a[1], a[2], a[3], Qh + offA + ((kb + hiA) ^ xorA));
#pragma unroll
            for (int nt = 0; nt < 8; nt++) MMA_F16(sf[nt], a, b[nt]);
            LDSM_X4(a[0], a[1], a[2], a[3], Ql + offA + ((kb + hiA) ^ xorA));
#pragma unroll
            for (int nt = 0; nt < 8; nt++) MMA_F16(sf[nt], a, b[nt]);
        }

        // ---- online softmax ----
        uint32_t ph[2][8], pl[2][8];
#pragma unroll
        for (int i = 0; i < 2; i++) {
            float mx = -1e30f;
#pragma unroll
            for (int nt = 0; nt < 8; nt++)
                mx = fmaxf(mx, fmaxf(sf[nt][2 * i], sf[nt][2 * i + 1]));
            mx = fmaxf(mx, __shfl_xor_sync(0xffffffffu, mx, 1));
            mx = fmaxf(mx, __shfl_xor_sync(0xffffffffu, mx, 2));
            float mnew = fmaxf(m_[i], mx);
            float corr = __expf(m_[i] - mnew);
            m_[i] = mnew;
            float rs = 0.0f;
#pragma unroll
            for (int nt = 0; nt < 8; nt++) {
                float p0 = __expf(sf[nt][2 * i]     - mnew);
                float p1 = __expf(sf[nt][2 * i + 1] - mnew);
                rs += p0 + p1;
                __half h0 = __float2half(p0), h1 = __float2half(p1);
                float f0 = __half2float(h0), f1 = __half2float(h1);
                ph[i][nt] = ((uint32_t)__half_as_ushort(h1) << 16) | __half_as_ushort(h0);
                pl[i][nt] = pack_h2(p0 - f0, p1 - f1);
            }
            rs += __shfl_xor_sync(0xffffffffu, rs, 1);
            rs += __shfl_xor_sync(0xffffffffu, rs, 2);
            l_[i] = l_[i] * corr + rs;
#pragma unroll
            for (int nt = 0; nt < 8; nt++) {
                of[nt][2 * i]     *= corr;
                of[nt][2 * i + 1] *= corr;
            }
        }

        // ---- PV: O += (ph+pl) vh ----
#pragma unroll
        for (int g = 0; g < 4; g++) {
            uint32_t ah[4] = { ph[0][2 * g], ph[1][2 * g], ph[0][2 * g + 1], ph[1][2 * g + 1] };
            uint32_t al[4] = { pl[0][2 * g], pl[1][2 * g], pl[0][2 * g + 1], pl[1][2 * g + 1] };
            const uint32_t kb = (uint32_t)g * 32u;
            uint32_t b[8][2];
#pragma unroll
            for (int nt = 0; nt < 8; nt++)
                LDSM_X2(b[nt][0], b[nt][1], VTH + (uint32_t)nt * 1024u + offBk + ((kb + hiB) ^ xorB));
#pragma unroll
            for (int nt = 0; nt < 8; nt++) MMA_F16(of[nt], ah, b[nt]);
#pragma unroll
            for (int nt = 0; nt < 8; nt++) MMA_F16(of[nt], al, b[nt]);
        }
        __syncthreads();
    }

    // ---- epilogue: normalize, split hi/lo -> g_ao [8192][2048] ----
    const float inv0 = 1.0f / l_[0], inv1 = 1.0f / l_[1];
    const int r = lane >> 2, c0 = (lane & 3) << 1;
    const int b_ = bh >> 4, h = bh & 15;
#pragma unroll
    for (int nt = 0; nt < 8; nt++) {
#pragma unroll
        for (int i = 0; i < 2; i++) {
            float inv = i ? inv1 : inv0;
            int n = qt * 128 + wm + r + i * 8;
            float v0 = of[nt][2 * i] * inv, v1 = of[nt][2 * i + 1] * inv;
            __half h0 = __float2half(v0), h1 = __float2half(v1);
            uint32_t Hp = ((uint32_t)__half_as_ushort(h1) << 16) | __half_as_ushort(h0);
            uint32_t Lp = pack_h2(v0 - __half2float(h0), v1 - __half2float(h1));
            __half* base = g_ao + ((size_t)(b_ * SEQ + n)) * K2 + h * HDIM + nt * 8 + c0;
            *(uint32_t*)(base)        = Hp;
            *(uint32_t*)(base + 1024) = Lp;
        }
    }
}

// ---------------------------------------------------------------------------
extern "C" void kernel_launch(void* const* d_in, const int* in_sizes, int n_in,
                              void* d_out, int out_size)
{
    (void)in_sizes; (void)n_in; (void)out_size;
    const float* x      = (const float*)d_in[0];
    const float* w_qkv  = (const float*)d_in[1];
    const float* w_proj = (const float*)d_in[2];
    const float* b_proj = (const float*)d_in[3];
    float* out = (float*)d_out;

    cudaFuncSetAttribute(gemm_mma<0>, cudaFuncAttributeMaxDynamicSharedMemorySize, GEMM_DSM);
    cudaFuncSetAttribute(gemm_mma<1>, cudaFuncAttributeMaxDynamicSharedMemorySize, GEMM_DSM);
    cudaFuncSetAttribute(flash_mma, cudaFuncAttributeMaxDynamicSharedMemorySize, FL_DSM);

    split_x<<<MTOT * DIM / 4 / 256, 256>>>(x);
    cast_w<0><<<3072 * DIM / 4 / 256, 256>>>(w_qkv);
    cast_w<1><<<1024 * DIM / 4 / 256, 256>>>(w_proj);

    gemm_mma<0><<<dim3(3072 / 128, MTOT / 128), 256, GEMM_DSM>>>(nullptr, nullptr);

    flash_mma<<<dim3(SEQ / 128, BH), 256, FL_DSM>>>();

    gemm_mma<1><<<dim3(1024 / 128, MTOT / 128), 256, GEMM_DSM>>>(b_proj, out);
}